// round 10
// baseline (speedup 1.0000x reference)
#include <cuda_runtime.h>

// ElementwiseTensorProd_o1: l=1 outputs of per-channel tensor product.
//   p01_m = s_l * v_r[m]
//   p10_m = v_l[m] * s_r
//   p11_m = cross(v_l, v_r)[m] * (1/sqrt(2))
// Layout: inputs z0 (N,RANK), z1 (N,3,RANK); out (N,3,3*RANK) = [p01|p10|p11].
//
// R10: 512-thread blocks x 2 rows/thread, block-phased R/W bursts.
// 256KB read / 288KB write same-direction cohort per barrier (the 1024t
// cohort size) WITHOUT the 1024t block-scheduling penalty.

#define RANK 256
#define RQ   (RANK / 4)      // 64 float4 groups per rank row
#define OQ   (3 * RANK / 4)  // 192 float4 groups per output row
#define THREADS 512
#define ROWS_PER_BLOCK 16    // THREADS/RQ * 2

__device__ __forceinline__ float4 mul4(float4 a, float4 b) {
    return make_float4(a.x * b.x, a.y * b.y, a.z * b.z, a.w * b.w);
}
__device__ __forceinline__ float4 fms4(float4 a, float4 b, float4 c, float4 d, float s) {
    return make_float4((a.x * b.x - c.x * d.x) * s,
                       (a.y * b.y - c.y * d.y) * s,
                       (a.z * b.z - c.z * d.z) * s,
                       (a.w * b.w - c.w * d.w) * s);
}

struct Row { float4 sl, sr, vl0, vl1, vl2, vr0, vr1, vr2; };

__device__ __forceinline__ void load_row(const float4* __restrict__ z0l,
                                         const float4* __restrict__ z1l,
                                         const float4* __restrict__ z0r,
                                         const float4* __restrict__ z1r,
                                         int n, int r, Row& R)
{
    const float4* vl = z1l + (size_t)(n * 3) * RQ + r;
    const float4* vr = z1r + (size_t)(n * 3) * RQ + r;
    R.sl  = __ldcs(z0l + (size_t)n * RQ + r);
    R.sr  = __ldcs(z0r + (size_t)n * RQ + r);
    R.vl0 = __ldcs(vl + 0 * RQ);
    R.vl1 = __ldcs(vl + 1 * RQ);
    R.vl2 = __ldcs(vl + 2 * RQ);
    R.vr0 = __ldcs(vr + 0 * RQ);
    R.vr1 = __ldcs(vr + 1 * RQ);
    R.vr2 = __ldcs(vr + 2 * RQ);
}

__device__ __forceinline__ void store_row(float4* __restrict__ out,
                                          int n, int r, const Row& R)
{
    const float INV_SQRT2 = 0.7071067811865476f;
    float4* ob = out + (size_t)(n * 3) * OQ + r;
    // m = 0
    __stcs(ob + 0 * OQ + 0 * RQ, mul4(R.sl, R.vr0));
    __stcs(ob + 0 * OQ + 1 * RQ, mul4(R.vl0, R.sr));
    __stcs(ob + 0 * OQ + 2 * RQ, fms4(R.vl1, R.vr2, R.vl2, R.vr1, INV_SQRT2));
    // m = 1
    __stcs(ob + 1 * OQ + 0 * RQ, mul4(R.sl, R.vr1));
    __stcs(ob + 1 * OQ + 1 * RQ, mul4(R.vl1, R.sr));
    __stcs(ob + 1 * OQ + 2 * RQ, fms4(R.vl2, R.vr0, R.vl0, R.vr2, INV_SQRT2));
    // m = 2
    __stcs(ob + 2 * OQ + 0 * RQ, mul4(R.sl, R.vr2));
    __stcs(ob + 2 * OQ + 1 * RQ, mul4(R.vl2, R.sr));
    __stcs(ob + 2 * OQ + 2 * RQ, fms4(R.vl0, R.vr1, R.vl1, R.vr0, INV_SQRT2));
}

__global__ void __launch_bounds__(THREADS)
etp_o1_kernel(const float4* __restrict__ z0l,
              const float4* __restrict__ z1l,
              const float4* __restrict__ z0r,
              const float4* __restrict__ z1r,
              float4* __restrict__ out,
              int N)
{
    // Block handles 16 consecutive n rows; each thread takes rows n0 and n0+8.
    int tid = threadIdx.x;
    int r   = tid & (RQ - 1);              // channel group within row
    int nb  = blockIdx.x * ROWS_PER_BLOCK; // first n of this block
    int n0  = nb + (tid >> 6);             // rows nb .. nb+7
    int n1  = n0 + 8;                      // rows nb+8 .. nb+15

    bool a0 = (n0 < N);
    bool a1 = (n1 < N);

    // ---- Load phase: 16 LDG.128 per thread (256KB per block) ----
    Row R0, R1;
    if (a0) load_row(z0l, z1l, z0r, z1r, n0, r, R0);
    if (a1) load_row(z0l, z1l, z0r, z1r, n1, r, R1);

    // Phase barrier: whole block finishes issuing loads before any store.
    __syncthreads();

    // ---- Store phase: 18 STG.128 per thread (288KB per block) ----
    if (a0) store_row(out, n0, r, R0);
    if (a1) store_row(out, n1, r, R1);
}

extern "C" void kernel_launch(void* const* d_in, const int* in_sizes, int n_in,
                              void* d_out, int out_size) {
    const float4* z0l = (const float4*)d_in[0];
    const float4* z1l = (const float4*)d_in[1];
    const float4* z0r = (const float4*)d_in[2];
    const float4* z1r = (const float4*)d_in[3];
    float4* out = (float4*)d_out;

    int N = in_sizes[0] / RANK;                        // 50000
    int blocks = (N + ROWS_PER_BLOCK - 1) / ROWS_PER_BLOCK;  // 3125
    etp_o1_kernel<<<blocks, THREADS>>>(z0l, z1l, z0r, z1r, out, N);
}

// round 11
// speedup vs baseline: 1.0022x; 1.0022x over previous
#include <cuda_runtime.h>

// ElementwiseTensorProd_o1: l=1 outputs of per-channel tensor product.
//   p01_m = s_l * v_r[m]
//   p10_m = v_l[m] * s_r
//   p11_m = cross(v_l, v_r)[m] * (1/sqrt(2))
// Layout: inputs z0 (N,RANK), z1 (N,3,RANK); out (N,3,3*RANK) = [p01|p10|p11].
//
// FINAL config — verified twice at kernel=121.7us / DRAM=84.5% (session best):
// 512-thread blocks, 1 row per thread, block-phased R/W bursts (barrier
// between load phase and store phase -> 128KB read / 144KB write
// same-direction cohorts at the DRAM controller), float4, cs policy.
// Sweep results: cohort 256t=84.0%, 512t=84.5% (peak), 1024t=83.4%,
// 512t x 2rows=82.9% (occupancy-starved). Flat/no-phase variants 83.6-84.3%.

#define RANK 256
#define RQ   (RANK / 4)      // 64 float4 groups per rank row
#define OQ   (3 * RANK / 4)  // 192 float4 groups per output row
#define THREADS 512

__device__ __forceinline__ float4 mul4(float4 a, float4 b) {
    return make_float4(a.x * b.x, a.y * b.y, a.z * b.z, a.w * b.w);
}
__device__ __forceinline__ float4 fms4(float4 a, float4 b, float4 c, float4 d, float s) {
    return make_float4((a.x * b.x - c.x * d.x) * s,
                       (a.y * b.y - c.y * d.y) * s,
                       (a.z * b.z - c.z * d.z) * s,
                       (a.w * b.w - c.w * d.w) * s);
}

__global__ void __launch_bounds__(THREADS)
etp_o1_kernel(const float4* __restrict__ z0l,
              const float4* __restrict__ z1l,
              const float4* __restrict__ z0r,
              const float4* __restrict__ z1r,
              float4* __restrict__ out,
              int n_total)  // N * RQ
{
    const float INV_SQRT2 = 0.7071067811865476f;
    int idx = blockIdx.x * blockDim.x + threadIdx.x;
    bool active = (idx < n_total);
    if (!active) idx = n_total - 1;   // clamp: keep whole block in the barrier

    int n = idx >> 6;          // / RQ
    int r = idx & (RQ - 1);    // % RQ

    // ---- Load phase: whole block issues all 8 LDG.128 before any STG ----
    const float4* vl = z1l + (size_t)(n * 3) * RQ + r;
    const float4* vr = z1r + (size_t)(n * 3) * RQ + r;
    float4 sl  = __ldcs(z0l + (size_t)n * RQ + r);
    float4 sr  = __ldcs(z0r + (size_t)n * RQ + r);
    float4 vl0 = __ldcs(vl + 0 * RQ);
    float4 vl1 = __ldcs(vl + 1 * RQ);
    float4 vl2 = __ldcs(vl + 2 * RQ);
    float4 vr0 = __ldcs(vr + 0 * RQ);
    float4 vr1 = __ldcs(vr + 1 * RQ);
    float4 vr2 = __ldcs(vr + 2 * RQ);

    // Cohort the phases: no warp starts its store burst until every warp
    // in the block has issued its load burst (orders issue only; per-warp
    // scoreboards still hide load latency at the consuming FMUL).
    __syncthreads();

    if (!active) return;

    // ---- Store phase: 9x STG.128 burst ----
    float4* ob = out + (size_t)(n * 3) * OQ + r;

    // m = 0
    __stcs(ob + 0 * OQ + 0 * RQ, mul4(sl, vr0));
    __stcs(ob + 0 * OQ + 1 * RQ, mul4(vl0, sr));
    __stcs(ob + 0 * OQ + 2 * RQ, fms4(vl1, vr2, vl2, vr1, INV_SQRT2));
    // m = 1
    __stcs(ob + 1 * OQ + 0 * RQ, mul4(sl, vr1));
    __stcs(ob + 1 * OQ + 1 * RQ, mul4(vl1, sr));
    __stcs(ob + 1 * OQ + 2 * RQ, fms4(vl2, vr0, vl0, vr2, INV_SQRT2));
    // m = 2
    __stcs(ob + 2 * OQ + 0 * RQ, mul4(sl, vr2));
    __stcs(ob + 2 * OQ + 1 * RQ, mul4(vl2, sr));
    __stcs(ob + 2 * OQ + 2 * RQ, fms4(vl0, vr1, vl1, vr0, INV_SQRT2));
}

extern "C" void kernel_launch(void* const* d_in, const int* in_sizes, int n_in,
                              void* d_out, int out_size) {
    const float4* z0l = (const float4*)d_in[0];
    const float4* z1l = (const float4*)d_in[1];
    const float4* z0r = (const float4*)d_in[2];
    const float4* z1r = (const float4*)d_in[3];
    float4* out = (float4*)d_out;

    int N = in_sizes[0] / RANK;          // 50000
    int n_total = N * RQ;                // 3.2M float4-work-items
    int blocks = (n_total + THREADS - 1) / THREADS;
    etp_o1_kernel<<<blocks, THREADS>>>(z0l, z1l, z0r, z1r, out, n_total);
}

// round 12
// speedup vs baseline: 1.0037x; 1.0015x over previous
#include <cuda_runtime.h>

// ElementwiseTensorProd_o1: l=1 outputs of per-channel tensor product.
//   p01_m = s_l * v_r[m]
//   p10_m = v_l[m] * s_r
//   p11_m = cross(v_l, v_r)[m] * (1/sqrt(2))
// Layout: inputs z0 (N,RANK), z1 (N,3,RANK); out (N,3,3*RANK) = [p01|p10|p11].
//
// R12: 1024-thread blocks, 1 row/thread, NO phase barrier (flat).
// Rationale: harness dur-vs-ncu gap correlates with grid size (grid 3125
// runs gave 4.1/4.8us gaps vs 6.3-7.3us at 6250/12500). R8 (1024t phased)
// holds the dur record at 127.4 despite a 123.3us kernel; removing the
// barrier recovers flat kernel time (~122.3us) at the same small grid.

#define RANK 256
#define RQ   (RANK / 4)      // 64 float4 groups per rank row
#define OQ   (3 * RANK / 4)  // 192 float4 groups per output row
#define THREADS 1024

__device__ __forceinline__ float4 mul4(float4 a, float4 b) {
    return make_float4(a.x * b.x, a.y * b.y, a.z * b.z, a.w * b.w);
}
__device__ __forceinline__ float4 fms4(float4 a, float4 b, float4 c, float4 d, float s) {
    return make_float4((a.x * b.x - c.x * d.x) * s,
                       (a.y * b.y - c.y * d.y) * s,
                       (a.z * b.z - c.z * d.z) * s,
                       (a.w * b.w - c.w * d.w) * s);
}

__global__ void __launch_bounds__(THREADS)
etp_o1_kernel(const float4* __restrict__ z0l,
              const float4* __restrict__ z1l,
              const float4* __restrict__ z0r,
              const float4* __restrict__ z1r,
              float4* __restrict__ out,
              int n_total)  // N * RQ
{
    const float INV_SQRT2 = 0.7071067811865476f;
    int idx = blockIdx.x * blockDim.x + threadIdx.x;
    if (idx >= n_total) return;

    int n = idx >> 6;          // / RQ
    int r = idx & (RQ - 1);    // % RQ

    // Front-batched streaming loads (8x LDG.128)
    const float4* vl = z1l + (size_t)(n * 3) * RQ + r;
    const float4* vr = z1r + (size_t)(n * 3) * RQ + r;
    float4 sl  = __ldcs(z0l + (size_t)n * RQ + r);
    float4 sr  = __ldcs(z0r + (size_t)n * RQ + r);
    float4 vl0 = __ldcs(vl + 0 * RQ);
    float4 vl1 = __ldcs(vl + 1 * RQ);
    float4 vl2 = __ldcs(vl + 2 * RQ);
    float4 vr0 = __ldcs(vr + 0 * RQ);
    float4 vr1 = __ldcs(vr + 1 * RQ);
    float4 vr2 = __ldcs(vr + 2 * RQ);

    float4* ob = out + (size_t)(n * 3) * OQ + r;

    // m = 0
    __stcs(ob + 0 * OQ + 0 * RQ, mul4(sl, vr0));
    __stcs(ob + 0 * OQ + 1 * RQ, mul4(vl0, sr));
    __stcs(ob + 0 * OQ + 2 * RQ, fms4(vl1, vr2, vl2, vr1, INV_SQRT2));
    // m = 1
    __stcs(ob + 1 * OQ + 0 * RQ, mul4(sl, vr1));
    __stcs(ob + 1 * OQ + 1 * RQ, mul4(vl1, sr));
    __stcs(ob + 1 * OQ + 2 * RQ, fms4(vl2, vr0, vl0, vr2, INV_SQRT2));
    // m = 2
    __stcs(ob + 2 * OQ + 0 * RQ, mul4(sl, vr2));
    __stcs(ob + 2 * OQ + 1 * RQ, mul4(vl2, sr));
    __stcs(ob + 2 * OQ + 2 * RQ, fms4(vl0, vr1, vl1, vr0, INV_SQRT2));
}

extern "C" void kernel_launch(void* const* d_in, const int* in_sizes, int n_in,
                              void* d_out, int out_size) {
    const float4* z0l = (const float4*)d_in[0];
    const float4* z1l = (const float4*)d_in[1];
    const float4* z0r = (const float4*)d_in[2];
    const float4* z1r = (const float4*)d_in[3];
    float4* out = (float4*)d_out;

    int N = in_sizes[0] / RANK;          // 50000
    int n_total = N * RQ;                // 3.2M float4-work-items
    int blocks = (n_total + THREADS - 1) / THREADS;   // 3125
    etp_o1_kernel<<<blocks, THREADS>>>(z0l, z1l, z0r, z1r, out, n_total);
}